// round 1
// baseline (speedup 1.0000x reference)
#include <cuda_runtime.h>

#define B_TOT 2048
#define N_WIN 64
#define C_DIM 192
#define C3 576
#define HEADS 6
#define HDIM 32
#define SCALE_F 0.17677669529663687f

// 302 MB scratch for the pre-conv QKV result t (B_TOT*N_WIN, C3)
__device__ float g_t[(size_t)B_TOT * N_WIN * C3];

// ---------------------------------------------------------------------------
// Kernel 1: t[m, o] = sum_k x[m, k] * qkv_w[o, k] + qkv_b[o]
//   M = 131072, K = 192, N = 576.  BM=128, BN=128, BK=16, 256 thr, 8x8/thread
// ---------------------------------------------------------------------------
#define BM 128
#define BN 128
#define BKK 16

__global__ __launch_bounds__(256) void qkv_gemm_kernel(
    const float* __restrict__ x, const float* __restrict__ w,
    const float* __restrict__ bias) {
  __shared__ float As[BKK][BM];
  __shared__ float Bs[BKK][BN];

  const int m0 = blockIdx.y * BM;
  const int n0 = blockIdx.x * BN;
  const int tid = threadIdx.x;
  const int tm = (tid >> 4) << 3;  // 0..120
  const int tn = (tid & 15) << 3;  // 0..120

  float acc[8][8];
#pragma unroll
  for (int i = 0; i < 8; i++)
#pragma unroll
    for (int j = 0; j < 8; j++) acc[i][j] = 0.f;

  for (int k0 = 0; k0 < 192; k0 += BKK) {
#pragma unroll
    for (int it = 0; it < 2; it++) {
      int idx = tid + (it << 8);     // 0..511
      int row = idx >> 2;            // 0..127
      int kk = (idx & 3) << 2;       // 0,4,8,12
      float4 va = *reinterpret_cast<const float4*>(
          x + (size_t)(m0 + row) * 192 + k0 + kk);
      As[kk + 0][row] = va.x; As[kk + 1][row] = va.y;
      As[kk + 2][row] = va.z; As[kk + 3][row] = va.w;

      int gn = n0 + row;
      float4 vb = make_float4(0.f, 0.f, 0.f, 0.f);
      if (gn < C3)
        vb = *reinterpret_cast<const float4*>(w + (size_t)gn * 192 + k0 + kk);
      Bs[kk + 0][row] = vb.x; Bs[kk + 1][row] = vb.y;
      Bs[kk + 2][row] = vb.z; Bs[kk + 3][row] = vb.w;
    }
    __syncthreads();

#pragma unroll
    for (int kk = 0; kk < BKK; kk++) {
      float a[8], b[8];
#pragma unroll
      for (int i = 0; i < 8; i++) a[i] = As[kk][tm + i];
#pragma unroll
      for (int j = 0; j < 8; j++) b[j] = Bs[kk][tn + j];
#pragma unroll
      for (int i = 0; i < 8; i++)
#pragma unroll
        for (int j = 0; j < 8; j++) acc[i][j] = fmaf(a[i], b[j], acc[i][j]);
    }
    __syncthreads();
  }

  // epilogue: + bias, guarded store (N=576 not a multiple of 128)
  float bv[8];
#pragma unroll
  for (int j = 0; j < 8; j++) {
    int gn = n0 + tn + j;
    bv[j] = (gn < C3) ? bias[gn] : 0.f;
  }
#pragma unroll
  for (int i = 0; i < 8; i++) {
    float* dst = g_t + (size_t)(m0 + tm + i) * C3 + n0 + tn;
#pragma unroll
    for (int j = 0; j < 8; j++) {
      if (n0 + tn + j < C3) dst[j] = acc[i][j] + bv[j];
    }
  }
}

// ---------------------------------------------------------------------------
// Kernel 2: per-window fused depthwise-conv + attention + projection
//   grid = 2048 blocks (one per window b), 384 threads.
//   smem: temp[64][588] (37632 f) then reused as Ws[192][196];
//         outa[64 rows, pitch 193] (alloc 12544 f). Total 50176 f = 200704 B.
// ---------------------------------------------------------------------------
#define TPITCH 588
#define OPITCH 193
#define WPITCH 196
#define TEMP_FLOATS (64 * TPITCH)   // 37632 == 192*196 (Ws fits exactly)
#define OUTA_FLOATS (64 * 196)      // 12544 (alloc; used pitch 193)

__global__ __launch_bounds__(384, 1) void attn_kernel(
    const float* __restrict__ mask, const float* __restrict__ dw_w,
    const float* __restrict__ dw_b, const float* __restrict__ rpb,
    const int* __restrict__ rel_idx, const float* __restrict__ proj_w,
    const float* __restrict__ proj_b, float* __restrict__ out) {
  extern __shared__ float sm[];
  float* temp = sm;                   // conv output (64 x 576, pitch 588)
  float* outa = sm + TEMP_FLOATS;     // attention output (64 x 192, pitch 193)

  const int tid = threadIdx.x;
  const int b = blockIdx.x;

  // ---------------- depthwise 3x3 conv over the (2048, 64) grid -----------
  // 1152 half-row slices: (nh in {0,1}) x (c in 0..575); 3 slices per thread.
#pragma unroll
  for (int rep = 0; rep < 3; rep++) {
    int item = tid + rep * 384;       // 0..1151
    int c = item % C3;
    int nh = item / C3;               // 0 or 1
    int nst = nh << 5;

    float wgt[9];
#pragma unroll
    for (int t = 0; t < 9; t++) wgt[t] = __ldg(dw_w + c * 9 + t);
    float bia = __ldg(dw_b + c);

    const float* p0 = g_t + c;
    float xm[3], x0[3];
#pragma unroll
    for (int r = 0; r < 3; r++) {
      int bb = b - 1 + r;
      bool v = ((unsigned)bb < (unsigned)B_TOT);
      xm[r] = (v && nst > 0) ? p0[((size_t)bb * 64 + nst - 1) * C3] : 0.f;
      x0[r] = v ? p0[((size_t)bb * 64 + nst) * C3] : 0.f;
    }
#pragma unroll 4
    for (int n = nst; n < nst + 32; n++) {
      float xp[3];
#pragma unroll
      for (int r = 0; r < 3; r++) {
        int bb = b - 1 + r;
        bool v = ((unsigned)bb < (unsigned)B_TOT) && (n + 1 < 64);
        xp[r] = v ? p0[((size_t)bb * 64 + n + 1) * C3] : 0.f;
      }
      float s = bia;
#pragma unroll
      for (int r = 0; r < 3; r++)
        s = fmaf(xm[r], wgt[r * 3 + 0],
            fmaf(x0[r], wgt[r * 3 + 1],
            fmaf(xp[r], wgt[r * 3 + 2], s)));
      temp[n * TPITCH + c] = s;
#pragma unroll
      for (int r = 0; r < 3; r++) { xm[r] = x0[r]; x0[r] = xp[r]; }
    }
  }
  __syncthreads();

  // ---------------- attention: 12 warps = 6 heads x 2 row-halves ----------
  {
    const int w = tid >> 5, lane = tid & 31;
    const int h = w >> 1;
    const int n = ((w & 1) << 5) | lane;

    const float* tq = temp + n * TPITCH + h * HDIM;
    float q[HDIM];
#pragma unroll
    for (int d = 0; d < HDIM; d++) q[d] = tq[d] * SCALE_F;

    const int* ri = rel_idx + n * 64;
    const float* mrow = mask + (size_t)(b & 63) * 4096 + n * 64;

    float rmax = -1e30f, rsum = 0.f;
    float acc[HDIM];
#pragma unroll
    for (int d = 0; d < HDIM; d++) acc[d] = 0.f;

#pragma unroll
    for (int mt = 0; mt < 64; mt += 16) {
      float s[16];
#pragma unroll
      for (int j = 0; j < 16; j++) {
        const float* tk = temp + (mt + j) * TPITCH + 192 + h * HDIM;
        float dot = 0.f;
#pragma unroll
        for (int d = 0; d < HDIM; d++) dot = fmaf(q[d], tk[d], dot);
        s[j] = dot + __ldg(rpb + __ldg(ri + mt + j) * 6 + h) +
               __ldg(mrow + mt + j);
      }
      float tmax = rmax;
#pragma unroll
      for (int j = 0; j < 16; j++) tmax = fmaxf(tmax, s[j]);
      float corr = __expf(rmax - tmax);
      rsum *= corr;
#pragma unroll
      for (int d = 0; d < HDIM; d++) acc[d] *= corr;
#pragma unroll
      for (int j = 0; j < 16; j++) {
        float p = __expf(s[j] - tmax);
        rsum += p;
        const float* tv = temp + (mt + j) * TPITCH + 384 + h * HDIM;
#pragma unroll
        for (int d = 0; d < HDIM; d++) acc[d] = fmaf(p, tv[d], acc[d]);
      }
      rmax = tmax;
    }
    float inv = 1.f / rsum;
    float* po = outa + n * OPITCH + h * HDIM;
#pragma unroll
    for (int d = 0; d < HDIM; d++) po[d] = acc[d] * inv;
  }
  __syncthreads();

  // ---------------- stage proj_w transposed into Ws[k][co] (pitch 196) ----
  float* Ws = temp;  // temp is dead; 192*196 = 37632 floats fits exactly
  for (int idx = tid; idx < 192 * 48; idx += 384) {
    int co = idx / 48;
    int k4 = (idx % 48) << 2;
    float4 v = *reinterpret_cast<const float4*>(proj_w + (size_t)co * 192 + k4);
    Ws[(k4 + 0) * WPITCH + co] = v.x;
    Ws[(k4 + 1) * WPITCH + co] = v.y;
    Ws[(k4 + 2) * WPITCH + co] = v.z;
    Ws[(k4 + 3) * WPITCH + co] = v.w;
  }
  __syncthreads();

  // ---------------- projection: out[n][co] = outa[n][:] . proj_w[co][:] ---
  {
    const int tn4 = (tid & 15) << 2;  // 4 rows
    const int tc8 = (tid >> 4) << 3;  // 8 cols (tid>>4 in 0..23)
    float fa[4][8];
#pragma unroll
    for (int i = 0; i < 4; i++)
#pragma unroll
      for (int j = 0; j < 8; j++) fa[i][j] = 0.f;

#pragma unroll 4
    for (int k = 0; k < 192; k++) {
      float a[4];
#pragma unroll
      for (int i = 0; i < 4; i++) a[i] = outa[(tn4 + i) * OPITCH + k];
      const float* wr = Ws + k * WPITCH + tc8;
      float wv[8];
#pragma unroll
      for (int j = 0; j < 8; j++) wv[j] = wr[j];
#pragma unroll
      for (int i = 0; i < 4; i++)
#pragma unroll
        for (int j = 0; j < 8; j++) fa[i][j] = fmaf(a[i], wv[j], fa[i][j]);
    }

    float pb[8];
#pragma unroll
    for (int j = 0; j < 8; j++) pb[j] = __ldg(proj_b + tc8 + j);

    float* ob = out + (size_t)b * (64 * C_DIM);
#pragma unroll
    for (int i = 0; i < 4; i++) {
      float4 v0, v1;
      v0.x = fa[i][0] + pb[0]; v0.y = fa[i][1] + pb[1];
      v0.z = fa[i][2] + pb[2]; v0.w = fa[i][3] + pb[3];
      v1.x = fa[i][4] + pb[4]; v1.y = fa[i][5] + pb[5];
      v1.z = fa[i][6] + pb[6]; v1.w = fa[i][7] + pb[7];
      float* dst = ob + (size_t)(tn4 + i) * C_DIM + tc8;
      *reinterpret_cast<float4*>(dst) = v0;
      *reinterpret_cast<float4*>(dst + 4) = v1;
    }
  }
}

// ---------------------------------------------------------------------------
extern "C" void kernel_launch(void* const* d_in, const int* in_sizes, int n_in,
                              void* d_out, int out_size) {
  const float* x      = (const float*)d_in[0];
  const float* mask   = (const float*)d_in[1];
  const float* qkv_w  = (const float*)d_in[2];
  const float* qkv_b  = (const float*)d_in[3];
  const float* dw_w   = (const float*)d_in[4];
  const float* dw_b   = (const float*)d_in[5];
  const float* rpb    = (const float*)d_in[6];
  const int*   rel    = (const int*)d_in[7];
  const float* proj_w = (const float*)d_in[8];
  const float* proj_b = (const float*)d_in[9];
  float* out = (float*)d_out;

  dim3 g1((C3 + BN - 1) / BN, (B_TOT * N_WIN) / BM);  // (5, 1024)
  qkv_gemm_kernel<<<g1, 256>>>(x, qkv_w, qkv_b);

  const int smem_bytes = (TEMP_FLOATS + OUTA_FLOATS) * 4;  // 200704
  cudaFuncSetAttribute(attn_kernel,
                       cudaFuncAttributeMaxDynamicSharedMemorySize, smem_bytes);
  attn_kernel<<<B_TOT, 384, smem_bytes>>>(mask, dw_w, dw_b, rpb, rel,
                                          proj_w, proj_b, out);
}

// round 2
// speedup vs baseline: 1.5333x; 1.5333x over previous
#include <cuda_runtime.h>
#include <cstdint>

#define B_TOT 2048
#define N_WIN 64
#define C_DIM 192
#define KDIM 192
#define C3 576
#define HEADS 6
#define HDIM 32
#define SCALE_F 0.17677669529663687f

// scratch: QKV pre-conv result t (B*N, 576) and attention output (B*N, 192)
__device__ float g_t[(size_t)B_TOT * N_WIN * C3];
__device__ float g_a[(size_t)B_TOT * N_WIN * C_DIM];

// ------------------------------- helpers ----------------------------------
__device__ __forceinline__ uint32_t f2tf32(float x) {
  uint32_t r;
  asm("cvt.rna.tf32.f32 %0, %1;" : "=r"(r) : "f"(x));
  return r;
}

typedef unsigned long long ull;

__device__ __forceinline__ ull pk(float x, float y) {
  ull r;
  asm("mov.b64 %0, {%1, %2};" : "=l"(r) : "f"(x), "f"(y));
  return r;
}
__device__ __forceinline__ float2 upk(ull v) {
  float2 r;
  asm("mov.b64 {%0, %1}, %2;" : "=f"(r.x), "=f"(r.y) : "l"(v));
  return r;
}
__device__ __forceinline__ void fma2(ull& d, ull a, ull b) {
  asm("fma.rn.f32x2 %0, %1, %2, %3;" : "=l"(d) : "l"(a), "l"(b), "l"(d));
}
__device__ __forceinline__ ull mul2(ull a, ull b) {
  ull d;
  asm("mul.rn.f32x2 %0, %1, %2;" : "=l"(d) : "l"(a), "l"(b));
  return d;
}
__device__ __forceinline__ ull add2(ull a, ull b) {
  ull d;
  asm("add.rn.f32x2 %0, %1, %2;" : "=l"(d) : "l"(a), "l"(b));
  return d;
}
__device__ __forceinline__ ull ld2g(const float* p) {
  float2 v = *reinterpret_cast<const float2*>(p);
  return pk(v.x, v.y);
}

// ---------------------------------------------------------------------------
// tf32 tensor-core GEMM: out[m, n] = sum_k A[m, k] * W[n, k] + bias[n]
//   M = 131072, K = 192, N in {576, 192}. BM=128, BN=64, BK=16,
//   256 threads = 8 warps (4m x 2n), each warp 32x32 via 2x4 m16n8k8 tiles.
// ---------------------------------------------------------------------------
#define GBM 128
#define GBN 64
#define GBK 16
#define APITCH 132
#define BPITCH 68

__global__ __launch_bounds__(256) void tf32_gemm_kernel(
    const float* __restrict__ A, const float* __restrict__ W,
    const float* __restrict__ bias, float* __restrict__ out, int Ncols) {
  __shared__ uint32_t As[GBK][APITCH];
  __shared__ uint32_t Bs[GBK][BPITCH];

  const int tid = threadIdx.x;
  const int m0 = blockIdx.y * GBM;
  const int n0 = blockIdx.x * GBN;
  const int wid = tid >> 5, lane = tid & 31;
  const int wm = (wid & 3) * 32;  // warp m-offset
  const int wn = (wid >> 2) * 32; // warp n-offset
  const int g = lane >> 2, tg = lane & 3;

  float acc[2][4][4];
#pragma unroll
  for (int i = 0; i < 2; i++)
#pragma unroll
    for (int j = 0; j < 4; j++)
#pragma unroll
      for (int r = 0; r < 4; r++) acc[i][j][r] = 0.f;

  const int am = tid >> 1;        // 0..127
  const int ak = (tid & 1) * 8;   // 0 or 8
  const int bn = tid >> 2;        // 0..63
  const int bk = (tid & 3) * 4;   // 0,4,8,12

  for (int k0 = 0; k0 < KDIM; k0 += GBK) {
    {
      const float* pa = A + (size_t)(m0 + am) * KDIM + k0 + ak;
      float4 a0 = *reinterpret_cast<const float4*>(pa);
      float4 a1 = *reinterpret_cast<const float4*>(pa + 4);
      As[ak + 0][am] = f2tf32(a0.x); As[ak + 1][am] = f2tf32(a0.y);
      As[ak + 2][am] = f2tf32(a0.z); As[ak + 3][am] = f2tf32(a0.w);
      As[ak + 4][am] = f2tf32(a1.x); As[ak + 5][am] = f2tf32(a1.y);
      As[ak + 6][am] = f2tf32(a1.z); As[ak + 7][am] = f2tf32(a1.w);
      const float* pb = W + (size_t)(n0 + bn) * KDIM + k0 + bk;
      float4 b0 = *reinterpret_cast<const float4*>(pb);
      Bs[bk + 0][bn] = f2tf32(b0.x); Bs[bk + 1][bn] = f2tf32(b0.y);
      Bs[bk + 2][bn] = f2tf32(b0.z); Bs[bk + 3][bn] = f2tf32(b0.w);
    }
    __syncthreads();

#pragma unroll
    for (int ks = 0; ks < GBK; ks += 8) {
      uint32_t af[2][4], bf[4][2];
#pragma unroll
      for (int mt = 0; mt < 2; mt++) {
        int m = wm + mt * 16 + g;
        af[mt][0] = As[ks + tg][m];
        af[mt][1] = As[ks + tg][m + 8];
        af[mt][2] = As[ks + tg + 4][m];
        af[mt][3] = As[ks + tg + 4][m + 8];
      }
#pragma unroll
      for (int nt = 0; nt < 4; nt++) {
        int nn = wn + nt * 8 + g;
        bf[nt][0] = Bs[ks + tg][nn];
        bf[nt][1] = Bs[ks + tg + 4][nn];
      }
#pragma unroll
      for (int mt = 0; mt < 2; mt++)
#pragma unroll
        for (int nt = 0; nt < 4; nt++) {
          asm volatile(
              "mma.sync.aligned.m16n8k8.row.col.f32.tf32.tf32.f32 "
              "{%0,%1,%2,%3}, {%4,%5,%6,%7}, {%8,%9}, {%0,%1,%2,%3};"
              : "+f"(acc[mt][nt][0]), "+f"(acc[mt][nt][1]),
                "+f"(acc[mt][nt][2]), "+f"(acc[mt][nt][3])
              : "r"(af[mt][0]), "r"(af[mt][1]), "r"(af[mt][2]),
                "r"(af[mt][3]), "r"(bf[nt][0]), "r"(bf[nt][1]));
        }
    }
    __syncthreads();
  }

  // epilogue (+bias), all dims divide evenly -> no guards
#pragma unroll
  for (int mt = 0; mt < 2; mt++) {
#pragma unroll
    for (int nt = 0; nt < 4; nt++) {
      int row = m0 + wm + mt * 16 + g;
      int col = n0 + wn + nt * 8 + 2 * tg;
      float2 bv = *reinterpret_cast<const float2*>(bias + col);
      float2 v0, v1;
      v0.x = acc[mt][nt][0] + bv.x; v0.y = acc[mt][nt][1] + bv.y;
      v1.x = acc[mt][nt][2] + bv.x; v1.y = acc[mt][nt][3] + bv.y;
      *reinterpret_cast<float2*>(out + (size_t)row * Ncols + col) = v0;
      *reinterpret_cast<float2*>(out + (size_t)(row + 8) * Ncols + col) = v1;
    }
  }
}

// ---------------------------------------------------------------------------
// Kernel 2: per-window depthwise conv + flash attention (f32x2 packed math)
//   grid = 2048 blocks, 384 threads, smem = temp[64][588] = 150528 B
// ---------------------------------------------------------------------------
#define TPITCH 588
#define TEMP_FLOATS (64 * TPITCH)

__global__ __launch_bounds__(384, 1) void attn_kernel(
    const float* __restrict__ mask, const float* __restrict__ dw_w,
    const float* __restrict__ dw_b, const float* __restrict__ rpb,
    const int* __restrict__ rel_idx, float* __restrict__ ga) {
  extern __shared__ float sm[];
  float* temp = sm;  // conv output (64 x 576, pitch 588)

  const int tid = threadIdx.x;
  const int b = blockIdx.x;

  // -------- depthwise 3x3 conv, 2 channels per work item via f32x2 --------
  for (int i = tid; i < 576; i += 384) {
    const int c0 = (i % 288) * 2;
    const int nst = (i / 288) << 5;

    ull w2[9];
#pragma unroll
    for (int t = 0; t < 9; t++)
      w2[t] = pk(__ldg(dw_w + c0 * 9 + t), __ldg(dw_w + c0 * 9 + 9 + t));
    ull bia2 = pk(__ldg(dw_b + c0), __ldg(dw_b + c0 + 1));

    const float* p0 = g_t + c0;
    ull xm[3], x0[3];
#pragma unroll
    for (int r = 0; r < 3; r++) {
      int bb = b - 1 + r;
      bool v = ((unsigned)bb < (unsigned)B_TOT);
      xm[r] = (v && nst > 0) ? ld2g(p0 + ((size_t)bb * 64 + nst - 1) * C3) : 0ull;
      x0[r] = v ? ld2g(p0 + ((size_t)bb * 64 + nst) * C3) : 0ull;
    }
#pragma unroll 4
    for (int n = nst; n < nst + 32; n++) {
      ull xp[3];
#pragma unroll
      for (int r = 0; r < 3; r++) {
        int bb = b - 1 + r;
        bool v = ((unsigned)bb < (unsigned)B_TOT) && (n + 1 < 64);
        xp[r] = v ? ld2g(p0 + ((size_t)bb * 64 + n + 1) * C3) : 0ull;
      }
      // 3 independent chains of depth 3
      ull s0 = mul2(xm[0], w2[0]);
      fma2(s0, x0[0], w2[1]); fma2(s0, xp[0], w2[2]);
      ull s1 = mul2(xm[1], w2[3]);
      fma2(s1, x0[1], w2[4]); fma2(s1, xp[1], w2[5]);
      ull s2 = mul2(xm[2], w2[6]);
      fma2(s2, x0[2], w2[7]); fma2(s2, xp[2], w2[8]);
      ull s = add2(add2(s0, s1), add2(s2, bia2));
      *reinterpret_cast<float2*>(temp + n * TPITCH + c0) = upk(s);
#pragma unroll
      for (int r = 0; r < 3; r++) { xm[r] = x0[r]; x0[r] = xp[r]; }
    }
  }
  __syncthreads();

  // -------- attention: 12 warps = 6 heads x 2 query-halves ----------------
  {
    const int w = tid >> 5, lane = tid & 31;
    const int h = w >> 1;
    const int n = ((w & 1) << 5) | lane;

    const float2* tq = reinterpret_cast<const float2*>(temp + n * TPITCH + h * HDIM);
    ull q2[16];
#pragma unroll
    for (int d = 0; d < 16; d++) {
      float2 v = tq[d];
      q2[d] = pk(v.x * SCALE_F, v.y * SCALE_F);
    }

    const int* ri = rel_idx + n * 64;
    const float* mrow = mask + (size_t)(b & 63) * 4096 + n * 64;

    float rmax = -1e30f, rsum = 0.f;
    ull acc2[16];
#pragma unroll
    for (int d = 0; d < 16; d++) acc2[d] = 0ull;

#pragma unroll
    for (int mt = 0; mt < 64; mt += 16) {
      float s[16];
#pragma unroll
      for (int j = 0; j < 16; j++) {
        const ull* tk = reinterpret_cast<const ull*>(
            temp + (mt + j) * TPITCH + 192 + h * HDIM);
        ull dp[4] = {0ull, 0ull, 0ull, 0ull};
#pragma unroll
        for (int d = 0; d < 16; d++) fma2(dp[d & 3], q2[d], tk[d]);
        float2 f = upk(add2(add2(dp[0], dp[1]), add2(dp[2], dp[3])));
        s[j] = f.x + f.y + __ldg(rpb + __ldg(ri + mt + j) * 6 + h) +
               __ldg(mrow + mt + j);
      }
      float tmax = rmax;
#pragma unroll
      for (int j = 0; j < 16; j++) tmax = fmaxf(tmax, s[j]);
      float corr = __expf(rmax - tmax);
      rsum *= corr;
      ull corr2 = pk(corr, corr);
#pragma unroll
      for (int d = 0; d < 16; d++) acc2[d] = mul2(acc2[d], corr2);
#pragma unroll
      for (int j = 0; j < 16; j++) {
        float p = __expf(s[j] - tmax);
        rsum += p;
        ull p2 = pk(p, p);
        const ull* tv = reinterpret_cast<const ull*>(
            temp + (mt + j) * TPITCH + 384 + h * HDIM);
#pragma unroll
        for (int d = 0; d < 16; d++) fma2(acc2[d], p2, tv[d]);
      }
      rmax = tmax;
    }
    float inv = 1.f / rsum;
    float2* po = reinterpret_cast<float2*>(
        ga + ((size_t)b * 64 + n) * C_DIM + h * HDIM);
#pragma unroll
    for (int d = 0; d < 16; d++) {
      float2 v = upk(acc2[d]);
      v.x *= inv; v.y *= inv;
      po[d] = v;
    }
  }
}

// ---------------------------------------------------------------------------
extern "C" void kernel_launch(void* const* d_in, const int* in_sizes, int n_in,
                              void* d_out, int out_size) {
  const float* x      = (const float*)d_in[0];
  const float* mask   = (const float*)d_in[1];
  const float* qkv_w  = (const float*)d_in[2];
  const float* qkv_b  = (const float*)d_in[3];
  const float* dw_w   = (const float*)d_in[4];
  const float* dw_b   = (const float*)d_in[5];
  const float* rpb    = (const float*)d_in[6];
  const int*   rel    = (const int*)d_in[7];
  const float* proj_w = (const float*)d_in[8];
  const float* proj_b = (const float*)d_in[9];
  float* out = (float*)d_out;

  float* gt_ptr = nullptr;
  float* ga_ptr = nullptr;
  cudaGetSymbolAddress((void**)&gt_ptr, g_t);
  cudaGetSymbolAddress((void**)&ga_ptr, g_a);

  // 1) QKV GEMM (tf32 tensor cores): g_t = x @ qkv_w^T + qkv_b
  dim3 g1(C3 / GBN, (B_TOT * N_WIN) / GBM);  // (9, 1024)
  tf32_gemm_kernel<<<g1, 256>>>(x, qkv_w, qkv_b, gt_ptr, C3);

  // 2) depthwise conv + window attention (f32x2): g_a
  const int smem_bytes = TEMP_FLOATS * 4;  // 150528
  cudaFuncSetAttribute(attn_kernel,
                       cudaFuncAttributeMaxDynamicSharedMemorySize, smem_bytes);
  attn_kernel<<<B_TOT, 384, smem_bytes>>>(mask, dw_w, dw_b, rpb, rel, ga_ptr);

  // 3) projection GEMM (tf32): out = g_a @ proj_w^T + proj_b
  dim3 g3(C_DIM / GBN, (B_TOT * N_WIN) / GBM);  // (3, 1024)
  tf32_gemm_kernel<<<g3, 256>>>(ga_ptr, proj_w, proj_b, out, C_DIM);
}